// round 3
// baseline (speedup 1.0000x reference)
#include <cuda_runtime.h>

// CapsuleLayer collapse: routing softmax over a singleton axis is identically 1,
// so out = squash( s ),  s[b,j,k] = sum_{i,u} W[i,j,k,u] * x[b,u,i].
// GEMM: C[32 x 1024] = A[32 x 32768] * B[32768 x 1024], K = (i,u).

#define N_B   32
#define N_IU  16
#define N_IC  2048
#define N_NU  16
#define N_US  64
#define N_N   (N_NU * N_US)   // 1024
#define N_ICCH 32             // i-chunks (64 i each)

// Scratch (no allocation allowed): x transposed to [i][u][b], and K-split partials.
__device__ float g_xT[N_IC * N_IU * N_B];            // 4 MB
__device__ float g_part[N_ICCH][N_B][N_N];           // 4 MB

__device__ __forceinline__ unsigned long long fma2(unsigned long long a,
                                                   unsigned long long b,
                                                   unsigned long long c) {
    unsigned long long d;
    asm("fma.rn.f32x2 %0, %1, %2, %3;" : "=l"(d) : "l"(a), "l"(b), "l"(c));
    return d;
}
__device__ __forceinline__ unsigned long long dup2(float x) {
    unsigned long long d;
    asm("mov.b64 %0, {%1, %1};" : "=l"(d) : "f"(x));
    return d;
}

// ---------------------------------------------------------------------------
// Kernel 1: x[b][u][i] -> xT[i][u][b]   (classic 32x32 smem tile transpose)
// grid (64 i-tiles, 16 u), block (32, 32)
// ---------------------------------------------------------------------------
__global__ void transpose_x_kernel(const float* __restrict__ x) {
    __shared__ float tile[32][33];
    const int i0 = blockIdx.x * 32;
    const int u  = blockIdx.y;
    const int tx = threadIdx.x, ty = threadIdx.y;
    // read coalesced over i (tx), b = ty
    tile[ty][tx] = x[(size_t)ty * (N_IU * N_IC) + (size_t)u * N_IC + i0 + tx];
    __syncthreads();
    // write coalesced over b (tx), i = i0 + ty
    g_xT[(size_t)(i0 + ty) * (N_IU * N_B) + u * N_B + tx] = tile[tx][ty];
}

// ---------------------------------------------------------------------------
// Kernel 2: K-split GEMM partials with packed f32x2 FMAs.
// grid (32 i-chunks, 4 n-quarters), block 128 threads.
// Block tile: M=32 (all b), N=256 (4 j), K-chunk = 64 i * 16 u = 1024.
// Stage = 1 i (16 r rows), double-buffered smem, register prefetch.
// Thread micro-tile: 4 m  x 16 n  (n in 4 groups of 4, one per j).
// ---------------------------------------------------------------------------
__global__ void __launch_bounds__(128, 1) gemm_part_kernel(const float* __restrict__ W) {
    __shared__ float Ws[2][16 * 256];   // [r=u][n], row stride 256
    __shared__ float Xs[2][16 * 32];    // [r=u][b]

    const int t  = threadIdx.x;
    const int ic = blockIdx.x;          // i-chunk: i in [ic*64, ic*64+64)
    const int jq = blockIdx.y;          // n in [jq*256, jq*256+256)
    const int tx = t & 15;              // n-column group (16)
    const int ty = t >> 4;              // m-row group (8)
    const int kk = t & 63;              // loader: k index
    const int uh = t >> 6;              // loader: u half (0/1)

    const float* Wg = W + (size_t)(ic * 64) * 16384 + (size_t)jq * 4096
                        + (size_t)kk * 16 + (size_t)uh * 8;
    const float* Xg = g_xT + (size_t)(ic * 64) * (N_IU * N_B) + t * 4;

    unsigned long long acc[4][4][2];
    #pragma unroll
    for (int m = 0; m < 4; m++)
        #pragma unroll
        for (int g = 0; g < 4; g++) { acc[m][g][0] = 0ULL; acc[m][g][1] = 0ULL; }

    float4 wreg[8];
    float4 xreg;

    auto load_regs = [&](int s) {
        const float* wb = Wg + (size_t)s * 16384;
        #pragma unroll
        for (int jL = 0; jL < 4; jL++) {
            wreg[jL * 2 + 0] = *reinterpret_cast<const float4*>(wb + jL * 1024);
            wreg[jL * 2 + 1] = *reinterpret_cast<const float4*>(wb + jL * 1024 + 4);
        }
        xreg = *reinterpret_cast<const float4*>(Xg + s * (N_IU * N_B));
    };
    auto store_regs = [&](int buf) {
        float* WsB = Ws[buf];
        #pragma unroll
        for (int jL = 0; jL < 4; jL++)
            #pragma unroll
            for (int f = 0; f < 2; f++) {
                const float4 v = wreg[jL * 2 + f];
                const int u4 = uh * 2 + f;
                const int n  = jL * 64 + kk;   // lanes span kk -> consecutive banks
                WsB[(u4 * 4 + 0) * 256 + n] = v.x;
                WsB[(u4 * 4 + 1) * 256 + n] = v.y;
                WsB[(u4 * 4 + 2) * 256 + n] = v.z;
                WsB[(u4 * 4 + 3) * 256 + n] = v.w;
            }
        *reinterpret_cast<float4*>(Xs[buf] + t * 4) = xreg;
    };
    auto compute = [&](int buf) {
        const float* WsB = Ws[buf];
        const float* XsB = Xs[buf];
        #pragma unroll
        for (int r = 0; r < 16; r++) {
            const float4 a4 = *reinterpret_cast<const float4*>(XsB + r * 32 + ty * 4);
            unsigned long long ad[4];
            ad[0] = dup2(a4.x); ad[1] = dup2(a4.y); ad[2] = dup2(a4.z); ad[3] = dup2(a4.w);
            #pragma unroll
            for (int g = 0; g < 4; g++) {
                const float4 w4 = *reinterpret_cast<const float4*>(WsB + r * 256 + g * 64 + tx * 4);
                unsigned long long w01, w23;
                asm("mov.b64 %0, {%1, %2};" : "=l"(w01) : "f"(w4.x), "f"(w4.y));
                asm("mov.b64 %0, {%1, %2};" : "=l"(w23) : "f"(w4.z), "f"(w4.w));
                #pragma unroll
                for (int m = 0; m < 4; m++) {
                    acc[m][g][0] = fma2(ad[m], w01, acc[m][g][0]);
                    acc[m][g][1] = fma2(ad[m], w23, acc[m][g][1]);
                }
            }
        }
    };

    load_regs(0);
    store_regs(0);
    __syncthreads();

    #pragma unroll 2
    for (int s = 0; s < 64; s++) {
        const int cur = s & 1;
        if (s + 1 < 64) load_regs(s + 1);        // prefetch next stage (LDG in flight)
        compute(cur);
        if (s + 1 < 64) {
            store_regs(cur ^ 1);
            __syncthreads();
        }
    }

    // epilogue: deterministic partials
    float* outp = &g_part[ic][0][0];
    #pragma unroll
    for (int m = 0; m < 4; m++) {
        const int bb = ty * 4 + m;
        #pragma unroll
        for (int g = 0; g < 4; g++) {
            union { unsigned long long u; float2 f; } c0, c1;
            c0.u = acc[m][g][0]; c1.u = acc[m][g][1];
            const float4 o = make_float4(c0.f.x, c0.f.y, c1.f.x, c1.f.y);
            *reinterpret_cast<float4*>(outp + (size_t)bb * N_N + jq * 256 + g * 64 + tx * 4) = o;
        }
    }
}

// ---------------------------------------------------------------------------
// Kernel 3: sum K-split partials, then squash.
// squash sums squared magnitude over the NUM_UNITS (j) axis per (b, k):
//   msq[b,k] = sum_j s[b,j,k]^2 ;  out = s * msq / ((1+msq) * sqrt(msq))
// grid 32 (b), block 1024 (n = j*64 + k)
// ---------------------------------------------------------------------------
__global__ void reduce_squash_kernel(float* __restrict__ out) {
    const int b = blockIdx.x;
    const int n = threadIdx.x;

    float s = 0.0f;
    #pragma unroll
    for (int ic = 0; ic < N_ICCH; ic++)
        s += g_part[ic][b][n];

    __shared__ float sm[N_N];
    __shared__ float msq[N_US];
    sm[n] = s;
    __syncthreads();
    if (n < N_US) {
        float m = 0.0f;
        #pragma unroll
        for (int j = 0; j < N_NU; j++) {
            const float v = sm[j * N_US + n];
            m += v * v;
        }
        msq[n] = m;
    }
    __syncthreads();
    const float m = msq[n & (N_US - 1)];
    out[(size_t)b * N_N + n] = s * m / ((1.0f + m) * sqrtf(m));
}

// ---------------------------------------------------------------------------
extern "C" void kernel_launch(void* const* d_in, const int* in_sizes, int n_in,
                              void* d_out, int out_size) {
    const float* x = (const float*)d_in[0];
    const float* W = (const float*)d_in[1];
    if (n_in >= 2 && in_sizes[0] > in_sizes[1]) {   // safety: x is the smaller input
        x = (const float*)d_in[1];
        W = (const float*)d_in[0];
    }
    transpose_x_kernel<<<dim3(N_IC / 32, N_IU), dim3(32, 32)>>>(x);
    gemm_part_kernel<<<dim3(N_ICCH, 4), 128>>>(W);
    reduce_squash_kernel<<<N_B, N_N>>>((float*)d_out);
}